// round 7
// baseline (speedup 1.0000x reference)
#include <cuda_runtime.h>
#include <math_constants.h>

#define N_NODES 1000000
#define N_EDGES 32000000
#define H 20
#define NREG 21      // H thresholds -> up to H+1 regions
#define NBPMAX 448   // >= NREG*H + H candidate breakpoints

#define EDGES_PER_THREAD 8
#define EDGE_BLOCKS (N_EDGES / EDGES_PER_THREAD / 256)   // 15625

// Scratch (no cudaMalloc allowed). Zero-initialized at module load;
// node_kernel re-zeroes g_agg after consuming it so every graph replay
// starts from a clean accumulator.
__device__ float  g_agg[N_NODES];
__device__ int    g_nb;                 // number of deduped breakpoints
__device__ float  g_sb[NBPMAX + 2];     // [-inf, bp..., +inf]
__device__ float2 g_si[NBPMAX + 1];     // per-interval (slope, intercept)

// ---------------------------------------------------------------------------
// Fused kernel. Edge blocks: scatter-add agg[dst] += x[src] (at the per-SM
// LSU scattered-lane-op floor ~250us). One extra block collapses the ENTIRE
// MLP into a global piecewise-linear function of the scalar h:
//   out(h) = S_i * h + T_i   for h in [sb_i, sb_{i+1})
// Breakpoints = layer-1 thresholds + zeros of each region's layer-2 affine
// pre-activations, sorted + deduped. Fully hidden under the edge work.
// ---------------------------------------------------------------------------
__global__ void edge_precompute_kernel(const int* __restrict__ ei,
                                       const float* __restrict__ x,
                                       const float* __restrict__ w1,
                                       const float* __restrict__ b1,
                                       const float* __restrict__ w2,
                                       const float* __restrict__ b2,
                                       const float* __restrict__ w3,
                                       const float* __restrict__ b3) {
    if (blockIdx.x < EDGE_BLOCKS) {
        // ----- edge path: 8 edges/thread, flat -----
        const int4* src4 = (const int4*)(ei);
        const int4* dst4 = (const int4*)(ei + N_EDGES);
        int t = blockIdx.x * blockDim.x + threadIdx.x;
        int j = t * 2;
        int4 s0 = __ldcs(&src4[j]);
        int4 s1 = __ldcs(&src4[j + 1]);
        int4 d0 = __ldcs(&dst4[j]);
        int4 d1 = __ldcs(&dst4[j + 1]);
        float v0 = __ldg(&x[s0.x]);
        float v1 = __ldg(&x[s0.y]);
        float v2 = __ldg(&x[s0.z]);
        float v3 = __ldg(&x[s0.w]);
        float v4 = __ldg(&x[s1.x]);
        float v5 = __ldg(&x[s1.y]);
        float v6 = __ldg(&x[s1.z]);
        float v7 = __ldg(&x[s1.w]);
        atomicAdd(&g_agg[d0.x], v0);
        atomicAdd(&g_agg[d0.y], v1);
        atomicAdd(&g_agg[d0.z], v2);
        atomicAdd(&g_agg[d0.w], v3);
        atomicAdd(&g_agg[d1.x], v4);
        atomicAdd(&g_agg[d1.y], v5);
        atomicAdd(&g_agg[d1.z], v6);
        atomicAdd(&g_agg[d1.w], v7);
        return;
    }

    // ----- precompute path (one block of 256 threads) -----
    __shared__ float  t[H];
    __shared__ int    cls[H];   // 0: w1>0, 1: w1<0, 2: w1==0 on, 3: off
    __shared__ int    pos[H];
    __shared__ float  sw1[H], sb1[H];
    __shared__ float  ssort[H];
    __shared__ int    s_nf, s_nc, s_nb;
    __shared__ float2 sAB[NREG * H];
    __shared__ float  cand[NBPMAX];
    __shared__ float  sorted[NBPMAX];
    __shared__ float  sbp[NBPMAX + 2];
    int tid = threadIdx.x;

    // phase 1: thresholds & classes
    if (tid < H) {
        float w = w1[tid], b = b1[tid];
        sw1[tid] = w; sb1[tid] = b;
        if (w > 0.0f)      { cls[tid] = 0; t[tid] = -b / w; }
        else if (w < 0.0f) { cls[tid] = 1; t[tid] = -b / w; }
        else               { cls[tid] = (b > 0.0f) ? 2 : 3; t[tid] = 0.0f; }
        ssort[tid] = CUDART_INF_F;
    }
    __syncthreads();
    if (tid == 0) {
        int c = 0;
        for (int k = 0; k < H; k++) if (cls[k] < 2) c++;
        s_nf = c; s_nc = 0;
    }
    if (tid < H && cls[tid] < 2) {
        float tk = t[tid];
        int p = 0;
        for (int m = 0; m < H; m++) {
            if (cls[m] < 2) {
                float tm = t[m];
                if (tm < tk || (tm == tk && m < tid)) p++;
            }
        }
        pos[tid]  = p;
        ssort[p]  = tk;
    }
    __syncthreads();
    int nf = s_nf;

    // phase 2: per-region affine maps of layer-2 preacts
    for (int e = tid; e < NREG * H; e += 256) {
        int r = e / H, j = e % H;
        float A = 0.0f;
        float B = __ldg(&b2[j]);
        for (int k = 0; k < H; k++) {
            int c = cls[k];
            bool m;
            if (c == 0)      m = (pos[k] <  r);
            else if (c == 1) m = (pos[k] >= r);
            else             m = (c == 2);
            if (m) {
                float wkj = __ldg(&w2[k * H + j]);
                A = fmaf(sw1[k], wkj, A);
                B = fmaf(sb1[k], wkj, B);
            }
        }
        sAB[e] = make_float2(A, B);
    }
    __syncthreads();

    // phase 3: collect candidate breakpoints
    if (tid < nf) { int p = atomicAdd(&s_nc, 1); cand[p] = ssort[tid]; }
    for (int e = tid; e < (nf + 1) * H; e += 256) {
        int r = e / H, j = e % H;
        float A = sAB[r * H + j].x, B = sAB[r * H + j].y;
        float lo = (r == 0)  ? -CUDART_INF_F : ssort[r - 1];
        float hi = (r == nf) ?  CUDART_INF_F : ssort[r];
        if (A != 0.0f) {
            float z = -B / A;
            if (z > lo && z < hi) { int p = atomicAdd(&s_nc, 1); cand[p] = z; }
        }
    }
    __syncthreads();
    int nc = s_nc;

    // phase 4: rank sort
    for (int e = tid; e < nc; e += 256) {
        float v = cand[e];
        int rk = 0;
        for (int m = 0; m < nc; m++) {
            float u = cand[m];
            rk += (u < v || (u == v && m < e)) ? 1 : 0;
        }
        sorted[rk] = v;
    }
    __syncthreads();

    // phase 5: dedup + sentinels
    if (tid == 0) {
        int nb = 0;
        for (int i = 0; i < nc; i++) {
            if (i == 0 || sorted[i] != sorted[i - 1]) sbp[1 + nb++] = sorted[i];
        }
        sbp[0] = -CUDART_INF_F;
        sbp[nb + 1] = CUDART_INF_F;
        s_nb = nb;
        g_nb = nb;
    }
    __syncthreads();
    int nb = s_nb;
    for (int e = tid; e < nb + 2; e += 256) g_sb[e] = sbp[e];

    // phase 6: per-interval slope/intercept via interior probe
    float b3v = __ldg(&b3[0]);
    for (int i = tid; i <= nb; i += 256) {
        float probe;
        if (nb == 0)       probe = 0.0f;
        else if (i == 0)   probe = sbp[1] - 1.0f;
        else if (i == nb)  probe = sbp[nb] + 1.0f;
        else               probe = 0.5f * (sbp[i] + sbp[i + 1]);
        int r = 0;
        for (int k = 0; k < nf; k++) r += (ssort[k] < probe) ? 1 : 0;
        float S = 0.0f, T = b3v;
        for (int j = 0; j < H; j++) {
            float A = sAB[r * H + j].x, B = sAB[r * H + j].y;
            if (fmaf(A, probe, B) > 0.0f) {
                float w = __ldg(&w3[j]);
                S = fmaf(w, A, S);
                T = fmaf(w, B, T);
            }
        }
        g_si[i] = make_float2(S, T);
    }
}

// ---------------------------------------------------------------------------
// Per node, 4 nodes/thread (float4 I/O): h = (1+eps)*x + agg, then binary
// search over deduped breakpoints + ONE fma: out = S*h + T.
// Re-zeroes g_agg for the next replay.
// ---------------------------------------------------------------------------
__global__ void node_kernel(float* __restrict__ out,
                            const float* __restrict__ x,
                            const float* __restrict__ eps) {
    __shared__ float  sb_s[NBPMAX + 2];
    __shared__ float2 si_s[NBPMAX + 1];
    __shared__ int    nb_s;
    if (threadIdx.x == 0) nb_s = g_nb;
    __syncthreads();
    int nb = nb_s;
    for (int e = threadIdx.x; e < nb + 2; e += blockDim.x) sb_s[e] = g_sb[e];
    for (int e = threadIdx.x; e <= nb;    e += blockDim.x) si_s[e] = g_si[e];
    float ev = 1.0f + __ldg(eps);
    __syncthreads();

    int i4 = blockIdx.x * blockDim.x + threadIdx.x;
    if (i4 < N_NODES / 4) {
        float4 xv = ((const float4*)x)[i4];
        float4 av = ((float4*)g_agg)[i4];
        ((float4*)g_agg)[i4] = make_float4(0.f, 0.f, 0.f, 0.f);

        float hv[4] = { fmaf(ev, xv.x, av.x), fmaf(ev, xv.y, av.y),
                        fmaf(ev, xv.z, av.z), fmaf(ev, xv.w, av.w) };
        float ov[4];
        #pragma unroll
        for (int n = 0; n < 4; n++) {
            float h = hv[n];
            int l = 0, r = nb;
            while (l < r) {                   // lower-bound: largest i with sb[i] <= h
                int m = (l + r + 1) >> 1;
                if (sb_s[m] <= h) l = m; else r = m - 1;
            }
            float2 st = si_s[l];
            ov[n] = fmaf(st.x, h, st.y);
        }
        ((float4*)out)[i4] = make_float4(ov[0], ov[1], ov[2], ov[3]);
    }
}

// ---------------------------------------------------------------------------
extern "C" void kernel_launch(void* const* d_in, const int* in_sizes, int n_in,
                              void* d_out, int out_size) {
    const float* x   = (const float*)d_in[0];
    const int*   ei  = (const int*)d_in[1];
    const float* eps = (const float*)d_in[2];
    const float* w1  = (const float*)d_in[3];
    const float* b1  = (const float*)d_in[4];
    const float* w2  = (const float*)d_in[5];
    const float* b2  = (const float*)d_in[6];
    const float* w3  = (const float*)d_in[7];
    const float* b3  = (const float*)d_in[8];
    float* out = (float*)d_out;

    edge_precompute_kernel<<<EDGE_BLOCKS + 1, 256>>>(ei, x, w1, b1, w2, b2, w3, b3);
    node_kernel<<<(N_NODES / 4 + 255) / 256, 256>>>(out, x, eps);
}